// round 15
// baseline (speedup 1.0000x reference)
#include <cuda_runtime.h>

// Problem constants
#define BATCH 2
#define CD    256      // channels c
#define HW    256      // h*w
#define TD    768      // n*d
#define O3    2304     // 3*TD
#define SCALE 0.125f   // 64^-0.5

// Scratch (no allocation allowed in kernel_launch)
__device__ float g_qkv[BATCH * O3 * HW];   // 4.7 MB
__device__ float g_att[BATCH * TD * HW];   // 1.5 MB

// pack two fp32 -> bf16x2 word {lo, hi}
__device__ __forceinline__ unsigned bf2(float hi, float lo) {
    unsigned d;
    asm("cvt.rn.bf16x2.f32 %0, %1, %2;" : "=r"(d) : "f"(hi), "f"(lo));
    return d;
}

__device__ __forceinline__ unsigned sptr(const void* p) {
    return (unsigned)__cvta_generic_to_shared(p);
}

__device__ __forceinline__ void ldsm4(unsigned* r, unsigned a) {
    asm volatile("ldmatrix.sync.aligned.m8n8.x4.shared.b16 {%0,%1,%2,%3}, [%4];"
                 : "=r"(r[0]), "=r"(r[1]), "=r"(r[2]), "=r"(r[3]) : "r"(a));
}
__device__ __forceinline__ void ldsm4t(unsigned* r, unsigned a) {
    asm volatile("ldmatrix.sync.aligned.m8n8.x4.trans.shared.b16 {%0,%1,%2,%3}, [%4];"
                 : "=r"(r[0]), "=r"(r[1]), "=r"(r[2]), "=r"(r[3]) : "r"(a));
}

// D(16x8,f32) += A(16x16,bf16 row) * B(16x8,bf16 col)
__device__ __forceinline__ void mma_bf16(float* d,
                                         unsigned a0, unsigned a1,
                                         unsigned a2, unsigned a3,
                                         unsigned b0, unsigned b1) {
    asm volatile(
        "mma.sync.aligned.m16n8k16.row.col.f32.bf16.bf16.f32 "
        "{%0,%1,%2,%3}, {%4,%5,%6,%7}, {%8,%9}, {%0,%1,%2,%3};"
        : "+f"(d[0]), "+f"(d[1]), "+f"(d[2]), "+f"(d[3])
        : "r"(a0), "r"(a1), "r"(a2), "r"(a3), "r"(b0), "r"(b1));
}

#define SROW  72   // smem row stride in bf16 (144 B: LDSM conflict-free)
#define SROWW 36   // in 32-bit words

// ---------------------------------------------------------------------------
// GEMM1 (bf16 HMMA + ldmatrix) — R10 config (best known): qkv = w_qkv @ x.
// Block tile 128(M)x64(N), BK=64, 256 threads = 8 warps (4M x 2N),
// warp tile 32x32.
// ---------------------------------------------------------------------------
__global__ __launch_bounds__(256) void gemm1_k(const float* __restrict__ A,
                                               const float* __restrict__ Bg,
                                               float* __restrict__ Cg)
{
    __shared__ unsigned As[128][SROWW];
    __shared__ unsigned Bs[64][SROWW];

    const int bz = blockIdx.z;
    const float* Bb = Bg + (size_t)bz * CD * HW;
    float*       Cb = Cg + (size_t)bz * O3 * HW;

    const int tid  = threadIdx.x;
    const int wid  = tid >> 5;
    const int lane = tid & 31;
    const int q    = lane >> 2;
    const int t    = lane & 3;
    const int m0   = (wid >> 1) * 32;
    const int n0   = (wid & 1) * 32;
    const int row0 = blockIdx.y * 128;
    const int col0 = blockIdx.x * 64;

    const int lrow = (lane & 7) + ((lane >> 3) & 1) * 8;
    const int lcol = (lane >> 4) * 8;
    const unsigned a_base = sptr(As) + (unsigned)(((m0 + lrow) * SROW + lcol) * 2);
    const unsigned b_base = sptr(Bs) + (unsigned)((lrow * SROW + n0 + lcol) * 2);

    float acc[2][4][4];
    #pragma unroll
    for (int im = 0; im < 2; im++)
        #pragma unroll
        for (int jn = 0; jn < 4; jn++)
            #pragma unroll
            for (int e = 0; e < 4; e++) acc[im][jn][e] = 0.f;

    float4 pa[8];
    float4 pb0[2], pb1[2];

    #define LDG_SLICE(k0)                                                        \
    {                                                                            \
        _Pragma("unroll")                                                        \
        for (int u = 0; u < 8; u++) {                                            \
            int idx = tid + u * 256;                                             \
            int m = idx >> 4, j4 = idx & 15;                                     \
            pa[u] = *(const float4*)&A[(size_t)(row0 + m) * CD + (k0) + j4 * 4]; \
        }                                                                        \
        _Pragma("unroll")                                                        \
        for (int u = 0; u < 2; u++) {                                            \
            int idx = tid + u * 256;                                             \
            int k2 = idx >> 4, n4 = idx & 15;                                    \
            const float* p = &Bb[(size_t)((k0) + 2 * k2) * HW + col0 + n4 * 4];  \
            pb0[u] = *(const float4*)p;                                          \
            pb1[u] = *(const float4*)(p + HW);                                   \
        }                                                                        \
    }

    #define STS_SLICE()                                                          \
    {                                                                            \
        _Pragma("unroll")                                                        \
        for (int u = 0; u < 8; u++) {                                            \
            int idx = tid + u * 256;                                             \
            int m = idx >> 4, j4 = idx & 15;                                     \
            uint2 w = {bf2(pa[u].y, pa[u].x), bf2(pa[u].w, pa[u].z)};            \
            *(uint2*)&As[m][j4 * 2] = w;                                         \
        }                                                                        \
        _Pragma("unroll")                                                        \
        for (int u = 0; u < 2; u++) {                                            \
            int idx = tid + u * 256;                                             \
            int k2 = idx >> 4, n4 = idx & 15;                                    \
            uint2 w0 = {bf2(pb0[u].y, pb0[u].x), bf2(pb0[u].w, pb0[u].z)};       \
            uint2 w1 = {bf2(pb1[u].y, pb1[u].x), bf2(pb1[u].w, pb1[u].z)};       \
            *(uint2*)&Bs[2 * k2][n4 * 2]     = w0;                               \
            *(uint2*)&Bs[2 * k2 + 1][n4 * 2] = w1;                               \
        }                                                                        \
    }

    LDG_SLICE(0);
    #pragma unroll
    for (int s = 0; s < 4; s++) {            // CD/64 = 4 slices
        STS_SLICE();
        __syncthreads();
        if (s + 1 < 4) LDG_SLICE((s + 1) * 64);

        #pragma unroll
        for (int ks = 0; ks < 4; ks++) {     // 4 k-steps of 16
            unsigned af[2][4], bfr[2][4];
            ldsm4(af[0], a_base + ks * 32);
            ldsm4(af[1], a_base + 16 * SROW * 2 + ks * 32);
            ldsm4t(bfr[0], b_base + ks * 16 * SROW * 2);
            ldsm4t(bfr[1], b_base + ks * 16 * SROW * 2 + 32);
            #pragma unroll
            for (int im = 0; im < 2; im++)
                #pragma unroll
                for (int jn = 0; jn < 4; jn++)
                    mma_bf16(acc[im][jn],
                             af[im][0], af[im][1], af[im][2], af[im][3],
                             bfr[jn >> 1][(jn & 1) * 2],
                             bfr[jn >> 1][(jn & 1) * 2 + 1]);
        }
        __syncthreads();
    }
    #undef LDG_SLICE
    #undef STS_SLICE

    #pragma unroll
    for (int im = 0; im < 2; im++) {
        int r = row0 + m0 + im * 16 + q;
        #pragma unroll
        for (int jn = 0; jn < 4; jn++) {
            int c = col0 + n0 + jn * 8 + 2 * t;
            float2 lo = {acc[im][jn][0], acc[im][jn][1]};
            float2 hi = {acc[im][jn][2], acc[im][jn][3]};
            *(float2*)&Cb[(size_t)r * HW + c]       = lo;
            *(float2*)&Cb[(size_t)(r + 8) * HW + c] = hi;
        }
    }
}

// ---------------------------------------------------------------------------
// Attention via moment expansion (degree 12). One warp per row (1536 rows).
// ---------------------------------------------------------------------------
#define NMOM 13
__global__ void attn_k()
{
    const int gtid = blockIdx.x * blockDim.x + threadIdx.x;
    const int row  = gtid >> 5;
    const int lane = threadIdx.x & 31;
    const int b = row / TD;
    const int r = row - b * TD;
    const float* base = g_qkv + (size_t)b * O3 * HW;
    const float4* q4 = (const float4*)(base + (size_t)r * HW);
    const float4* k4 = (const float4*)(base + (size_t)(TD + r) * HW);
    const float4* v4 = (const float4*)(base + (size_t)(2 * TD + r) * HW);

    float S[NMOM], T[NMOM];
    #pragma unroll
    for (int m = 0; m < NMOM; m++) { S[m] = 0.f; T[m] = 0.f; }

    #pragma unroll
    for (int c = 0; c < 2; c++) {
        float4 kk = k4[lane + 32 * c];
        float4 vv = v4[lane + 32 * c];
        float ks[4] = {kk.x, kk.y, kk.z, kk.w};
        float vs[4] = {vv.x, vv.y, vv.z, vv.w};
        #pragma unroll
        for (int e = 0; e < 4; e++) {
            float pw = 1.f;
            float kv = ks[e], vl = vs[e];
            #pragma unroll
            for (int m = 0; m < NMOM; m++) {
                S[m] = fmaf(pw, vl, S[m]);
                T[m] += pw;
                pw *= kv;
            }
        }
    }

    const float invf[NMOM] = {
        1.f, 1.f, 0.5f, 1.f/6.f, 1.f/24.f, 1.f/120.f, 1.f/720.f,
        1.f/5040.f, 1.f/40320.f, 1.f/362880.f, 1.f/3628800.f,
        1.f/39916800.f, 1.f/479001600.f };

    #pragma unroll
    for (int m = 0; m < NMOM; m++) {
        #pragma unroll
        for (int o = 16; o > 0; o >>= 1) {
            S[m] += __shfl_xor_sync(0xffffffffu, S[m], o);
            T[m] += __shfl_xor_sync(0xffffffffu, T[m], o);
        }
        S[m] *= invf[m];
        T[m] *= invf[m];
    }

    float* orow = g_att + (size_t)row * HW;
    #pragma unroll
    for (int c = 0; c < 2; c++) {
        float4 qq = q4[lane + 32 * c];
        float qs[4] = {qq.x, qq.y, qq.z, qq.w};
        float os[4];
        #pragma unroll
        for (int e = 0; e < 4; e++) {
            float p = qs[e] * SCALE;
            float num = S[NMOM - 1], den = T[NMOM - 1];
            #pragma unroll
            for (int m = NMOM - 2; m >= 0; m--) {
                num = fmaf(num, p, S[m]);
                den = fmaf(den, p, T[m]);
            }
            os[e] = __fdividef(num, den);
        }
        float4 o4 = {os[0], os[1], os[2], os[3]};
        *(float4*)&orow[(lane + 32 * c) * 4] = o4;
    }
}

// ---------------------------------------------------------------------------
// GEMM2 + bias + residual + LayerNorm, fully fused, y stays in registers.
// Each block owns a complete stripe: 16 channels x all 256 spatial cols,
// full K=768 (12 slices of 64). 256 threads = 8 N-warps (warp tile 16x32).
// After the MMA loop: add bias + x, block-wide mean/var per row, normalize
// fragments, write out directly. No y buffer, no atomics, no extra kernel.
// ---------------------------------------------------------------------------
#define BROW  264   // B smem stride in bf16 (528 B: LDSM-trans conflict-free)
#define BROWW 132
__global__ __launch_bounds__(256) void gemm2ln_k(const float* __restrict__ A,
                                                 const float* __restrict__ Bg,
                                                 const float* __restrict__ x,
                                                 const float* __restrict__ b_out,
                                                 float* __restrict__ out)
{
    __shared__ unsigned As[16][SROWW];        // 16 x 64 bf16
    __shared__ unsigned Bs[64 * BROWW];       // 64 x 264 bf16
    __shared__ float s_sum[16][9];
    __shared__ float s_sq[16][9];

    const int bz = blockIdx.y;
    const float* Bb = Bg + (size_t)bz * TD * HW;
    const int row0 = blockIdx.x * 16;

    const int tid  = threadIdx.x;
    const int wid  = tid >> 5;
    const int lane = tid & 31;
    const int q    = lane >> 2;
    const int t    = lane & 3;
    const int n0   = wid * 32;

    const int lrow = (lane & 7) + ((lane >> 3) & 1) * 8;
    const int lcol = (lane >> 4) * 8;
    const unsigned a_base = sptr(As) + (unsigned)((lrow * SROW + lcol) * 2);
    const unsigned b_base = sptr(Bs) + (unsigned)((lrow * BROW + n0 + lcol) * 2);

    float acc[4][4];
    #pragma unroll
    for (int jn = 0; jn < 4; jn++)
        #pragma unroll
        for (int e = 0; e < 4; e++) acc[jn][e] = 0.f;

    // fill coordinates
    const int am = tid >> 4, aj4 = tid & 15;        // A: 16 rows x 16 f4
    float4 pa;
    float4 pb[16];                                  // B: 64 rows x 64 f4

    #define LDG_S(k0)                                                           \
    {                                                                           \
        pa = *(const float4*)&A[(size_t)(row0 + am) * TD + (k0) + aj4 * 4];     \
        _Pragma("unroll")                                                       \
        for (int u = 0; u < 16; u++) {                                          \
            int idx = tid + u * 256;                                            \
            int k = idx >> 6, c4 = idx & 63;                                    \
            pb[u] = *(const float4*)&Bb[(size_t)((k0) + k) * HW + c4 * 4];      \
        }                                                                       \
    }

    #define STS_S()                                                             \
    {                                                                           \
        uint2 wa = {bf2(pa.y, pa.x), bf2(pa.w, pa.z)};                          \
        *(uint2*)&As[am][aj4 * 2] = wa;                                         \
        _Pragma("unroll")                                                       \
        for (int u = 0; u < 16; u++) {                                          \
            int idx = tid + u * 256;                                            \
            int k = idx >> 6, c4 = idx & 63;                                    \
            uint2 w = {bf2(pb[u].y, pb[u].x), bf2(pb[u].w, pb[u].z)};           \
            *(uint2*)&Bs[k * BROWW + c4 * 2] = w;                               \
        }                                                                       \
    }

    LDG_S(0);
    for (int s = 0; s < 12; s++) {           // TD/64 = 12 slices
        STS_S();
        __syncthreads();
        if (s + 1 < 12) LDG_S((s + 1) * 64);

        #pragma unroll
        for (int kq = 0; kq < 4; kq++) {
            unsigned af[4], bf0[4], bf1[4];
            ldsm4(af, a_base + kq * 32);
            ldsm4t(bf0, b_base + kq * 16 * BROW * 2);
            ldsm4t(bf1, b_base + kq * 16 * BROW * 2 + 32);
            mma_bf16(acc[0], af[0], af[1], af[2], af[3], bf0[0], bf0[1]);
            mma_bf16(acc[1], af[0], af[1], af[2], af[3], bf0[2], bf0[3]);
            mma_bf16(acc[2], af[0], af[1], af[2], af[3], bf1[0], bf1[1]);
            mma_bf16(acc[3], af[0], af[1], af[2], af[3], bf1[2], bf1[3]);
        }
        __syncthreads();
    }
    #undef LDG_S
    #undef STS_S

    // ---- fused bias + residual + LayerNorm ----
    const size_t gb = (size_t)bz * CD;
    const float bias_q  = b_out[row0 + q];
    const float bias_q8 = b_out[row0 + q + 8];
    const float* xr0 = x + (gb + row0 + q) * HW;
    const float* xr8 = x + (gb + row0 + q + 8) * HW;

    float s0 = 0.f, sq0 = 0.f, s8 = 0.f, sq8 = 0.f;
    #pragma unroll
    for (int jn = 0; jn < 4; jn++) {
        int c = n0 + jn * 8 + 2 * t;
        float2 xv0 = *(const float2*)&xr0[c];
        float2 xv8 = *(const float2*)&xr8[c];
        acc[jn][0] += xv0.x + bias_q;
        acc[jn][1] += xv0.y + bias_q;
        acc[jn][2] += xv8.x + bias_q8;
        acc[jn][3] += xv8.y + bias_q8;
        s0  += acc[jn][0] + acc[jn][1];
        sq0 += acc[jn][0] * acc[jn][0] + acc[jn][1] * acc[jn][1];
        s8  += acc[jn][2] + acc[jn][3];
        sq8 += acc[jn][2] * acc[jn][2] + acc[jn][3] * acc[jn][3];
    }
    // reduce across the 4 t-lanes sharing each row
    #pragma unroll
    for (int o = 1; o <= 2; o <<= 1) {
        s0  += __shfl_xor_sync(0xffffffffu, s0,  o);
        sq0 += __shfl_xor_sync(0xffffffffu, sq0, o);
        s8  += __shfl_xor_sync(0xffffffffu, s8,  o);
        sq8 += __shfl_xor_sync(0xffffffffu, sq8, o);
    }
    if (t == 0) {
        s_sum[q][wid]     = s0;  s_sq[q][wid]     = sq0;
        s_sum[q + 8][wid] = s8;  s_sq[q + 8][wid] = sq8;
    }
    __syncthreads();

    float m0 = 0.f, v0 = 0.f, m8 = 0.f, v8 = 0.f;
    #pragma unroll
    for (int w = 0; w < 8; w++) {
        m0 += s_sum[q][w];     v0 += s_sq[q][w];
        m8 += s_sum[q + 8][w]; v8 += s_sq[q + 8][w];
    }
    const float mean0 = m0 * (1.f / HW);
    const float var0  = v0 * (1.f / HW) - mean0 * mean0;
    const float inv0  = rsqrtf(var0 + 1e-5f);
    const float mean8 = m8 * (1.f / HW);
    const float var8  = v8 * (1.f / HW) - mean8 * mean8;
    const float inv8  = rsqrtf(var8 + 1e-5f);

    float* o0 = out + (gb + row0 + q) * HW;
    float* o8 = out + (gb + row0 + q + 8) * HW;
    #pragma unroll
    for (int jn = 0; jn < 4; jn++) {
        int c = n0 + jn * 8 + 2 * t;
        float2 w0 = {(acc[jn][0] - mean0) * inv0, (acc[jn][1] - mean0) * inv0};
        float2 w8 = {(acc[jn][2] - mean8) * inv8, (acc[jn][3] - mean8) * inv8};
        *(float2*)&o0[c] = w0;
        *(float2*)&o8[c] = w8;
    }
}

// ---------------------------------------------------------------------------
extern "C" void kernel_launch(void* const* d_in, const int* in_sizes, int n_in,
                              void* d_out, int out_size)
{
    const float* x     = (const float*)d_in[0];   // (2,256,16,16)
    const float* w_qkv = (const float*)d_in[1];   // (2304,256)
    const float* w_out = (const float*)d_in[2];   // (256,768)
    const float* b_out = (const float*)d_in[3];   // (256,)
    float* out = (float*)d_out;                   // (2,256,16,16) fp32

    float *qkv_p, *att_p;
    cudaGetSymbolAddress((void**)&qkv_p, g_qkv);
    cudaGetSymbolAddress((void**)&att_p, g_att);

    // 1) qkv = w_qkv @ x   (bf16 HMMA + LDSM, 144 blocks, R10 config)
    gemm1_k<<<dim3(HW / 64, O3 / 128, BATCH), 256>>>(w_qkv, x, qkv_p);

    // 2) moment-expansion attention, warp per row
    attn_k<<<(BATCH * TD * 32) / 256, 256>>>();

    // 3) y = w_out @ att + bias + x, LayerNorm — one fused kernel, 32 blocks
    gemm2ln_k<<<dim3(CD / 16, BATCH), 256>>>(w_out, att_p, x, b_out, out);
}

// round 16
// speedup vs baseline: 1.4467x; 1.4467x over previous
#include <cuda_runtime.h>

// Problem constants
#define BATCH 2
#define CD    256      // channels c
#define HW    256      // h*w
#define TD    768      // n*d
#define O3    2304     // 3*TD
#define SCALE 0.125f   // 64^-0.5

// Scratch (no allocation allowed in kernel_launch)
__device__ float g_qkv[BATCH * O3 * HW];   // 4.7 MB
__device__ float g_att[BATCH * TD * HW];   // 1.5 MB
__device__ float g_y  [BATCH * CD * HW];   // 0.5 MB

// pack two fp32 -> bf16x2 word {lo, hi}
__device__ __forceinline__ unsigned bf2(float hi, float lo) {
    unsigned d;
    asm("cvt.rn.bf16x2.f32 %0, %1, %2;" : "=r"(d) : "f"(hi), "f"(lo));
    return d;
}

__device__ __forceinline__ unsigned sptr(const void* p) {
    return (unsigned)__cvta_generic_to_shared(p);
}

__device__ __forceinline__ void ldsm4(unsigned* r, unsigned a) {
    asm volatile("ldmatrix.sync.aligned.m8n8.x4.shared.b16 {%0,%1,%2,%3}, [%4];"
                 : "=r"(r[0]), "=r"(r[1]), "=r"(r[2]), "=r"(r[3]) : "r"(a));
}
__device__ __forceinline__ void ldsm4t(unsigned* r, unsigned a) {
    asm volatile("ldmatrix.sync.aligned.m8n8.x4.trans.shared.b16 {%0,%1,%2,%3}, [%4];"
                 : "=r"(r[0]), "=r"(r[1]), "=r"(r[2]), "=r"(r[3]) : "r"(a));
}

// D(16x8,f32) += A(16x16,bf16 row) * B(16x8,bf16 col)
__device__ __forceinline__ void mma_bf16(float* d,
                                         unsigned a0, unsigned a1,
                                         unsigned a2, unsigned a3,
                                         unsigned b0, unsigned b1) {
    asm volatile(
        "mma.sync.aligned.m16n8k16.row.col.f32.bf16.bf16.f32 "
        "{%0,%1,%2,%3}, {%4,%5,%6,%7}, {%8,%9}, {%0,%1,%2,%3};"
        : "+f"(d[0]), "+f"(d[1]), "+f"(d[2]), "+f"(d[3])
        : "r"(a0), "r"(a1), "r"(a2), "r"(a3), "r"(b0), "r"(b1));
}

#define SROW  72   // smem row stride in bf16 (144 B: LDSM conflict-free)
#define SROWW 36   // in 32-bit words

// ---------------------------------------------------------------------------
// GEMM1 (bf16 HMMA + ldmatrix, fragment-pipelined): qkv = w_qkv @ x.
// A:[O3,CD] row-major, B:[b][CD,HW], C:[b][O3,HW]
// Block tile 128(M)x64(N), BK=64, 256 threads = 8 warps (4M x 2N),
// warp tile 32x32. LDSM for k-step ks+1 issued before MMAs of ks.
// ---------------------------------------------------------------------------
__global__ __launch_bounds__(256) void gemm1_k(const float* __restrict__ A,
                                               const float* __restrict__ Bg,
                                               float* __restrict__ Cg)
{
    __shared__ unsigned As[128][SROWW];
    __shared__ unsigned Bs[64][SROWW];

    const int bz = blockIdx.z;
    const float* Bb = Bg + (size_t)bz * CD * HW;
    float*       Cb = Cg + (size_t)bz * O3 * HW;

    const int tid  = threadIdx.x;
    const int wid  = tid >> 5;
    const int lane = tid & 31;
    const int q    = lane >> 2;
    const int t    = lane & 3;
    const int m0   = (wid >> 1) * 32;
    const int n0   = (wid & 1) * 32;
    const int row0 = blockIdx.y * 128;
    const int col0 = blockIdx.x * 64;

    const int lrow = (lane & 7) + ((lane >> 3) & 1) * 8;
    const int lcol = (lane >> 4) * 8;
    const unsigned a_base = sptr(As) + (unsigned)(((m0 + lrow) * SROW + lcol) * 2);
    const unsigned b_base = sptr(Bs) + (unsigned)((lrow * SROW + n0 + lcol) * 2);

    float acc[2][4][4];
    #pragma unroll
    for (int im = 0; im < 2; im++)
        #pragma unroll
        for (int jn = 0; jn < 4; jn++)
            #pragma unroll
            for (int e = 0; e < 4; e++) acc[im][jn][e] = 0.f;

    float4 pa[8];
    float4 pb0[2], pb1[2];

    #define LDG_SLICE(k0)                                                        \
    {                                                                            \
        _Pragma("unroll")                                                        \
        for (int u = 0; u < 8; u++) {                                            \
            int idx = tid + u * 256;                                             \
            int m = idx >> 4, j4 = idx & 15;                                     \
            pa[u] = *(const float4*)&A[(size_t)(row0 + m) * CD + (k0) + j4 * 4]; \
        }                                                                        \
        _Pragma("unroll")                                                        \
        for (int u = 0; u < 2; u++) {                                            \
            int idx = tid + u * 256;                                             \
            int k2 = idx >> 4, n4 = idx & 15;                                    \
            const float* p = &Bb[(size_t)((k0) + 2 * k2) * HW + col0 + n4 * 4];  \
            pb0[u] = *(const float4*)p;                                          \
            pb1[u] = *(const float4*)(p + HW);                                   \
        }                                                                        \
    }

    #define STS_SLICE()                                                          \
    {                                                                            \
        _Pragma("unroll")                                                        \
        for (int u = 0; u < 8; u++) {                                            \
            int idx = tid + u * 256;                                             \
            int m = idx >> 4, j4 = idx & 15;                                     \
            uint2 w = {bf2(pa[u].y, pa[u].x), bf2(pa[u].w, pa[u].z)};            \
            *(uint2*)&As[m][j4 * 2] = w;                                         \
        }                                                                        \
        _Pragma("unroll")                                                        \
        for (int u = 0; u < 2; u++) {                                            \
            int idx = tid + u * 256;                                             \
            int k2 = idx >> 4, n4 = idx & 15;                                    \
            uint2 w0 = {bf2(pb0[u].y, pb0[u].x), bf2(pb0[u].w, pb0[u].z)};       \
            uint2 w1 = {bf2(pb1[u].y, pb1[u].x), bf2(pb1[u].w, pb1[u].z)};       \
            *(uint2*)&Bs[2 * k2][n4 * 2]     = w0;                               \
            *(uint2*)&Bs[2 * k2 + 1][n4 * 2] = w1;                               \
        }                                                                        \
    }

    // fragment load for k-step ks into buffer d
    #define LDF1(d, ks)                                                          \
    {                                                                            \
        ldsm4(af[d][0], a_base + (ks) * 32);                                     \
        ldsm4(af[d][1], a_base + 16 * SROW * 2 + (ks) * 32);                     \
        ldsm4t(bfr[d][0], b_base + (ks) * 16 * SROW * 2);                        \
        ldsm4t(bfr[d][1], b_base + (ks) * 16 * SROW * 2 + 32);                   \
    }

    unsigned af[2][2][4], bfr[2][2][4];

    LDG_SLICE(0);
    #pragma unroll
    for (int s = 0; s < 4; s++) {            // CD/64 = 4 slices
        STS_SLICE();
        __syncthreads();
        if (s + 1 < 4) LDG_SLICE((s + 1) * 64);

        LDF1(0, 0);
        #pragma unroll
        for (int ks = 0; ks < 4; ks++) {     // 4 k-steps of 16
            const int cur = ks & 1;
            if (ks + 1 < 4) LDF1(cur ^ 1, ks + 1);
            #pragma unroll
            for (int im = 0; im < 2; im++)
                #pragma unroll
                for (int jn = 0; jn < 4; jn++)
                    mma_bf16(acc[im][jn],
                             af[cur][im][0], af[cur][im][1],
                             af[cur][im][2], af[cur][im][3],
                             bfr[cur][jn >> 1][(jn & 1) * 2],
                             bfr[cur][jn >> 1][(jn & 1) * 2 + 1]);
        }
        __syncthreads();
    }
    #undef LDG_SLICE
    #undef STS_SLICE
    #undef LDF1

    #pragma unroll
    for (int im = 0; im < 2; im++) {
        int r = row0 + m0 + im * 16 + q;
        #pragma unroll
        for (int jn = 0; jn < 4; jn++) {
            int c = col0 + n0 + jn * 8 + 2 * t;
            float2 lo = {acc[im][jn][0], acc[im][jn][1]};
            float2 hi = {acc[im][jn][2], acc[im][jn][3]};
            *(float2*)&Cb[(size_t)r * HW + c]       = lo;
            *(float2*)&Cb[(size_t)(r + 8) * HW + c] = hi;
        }
    }
}

// ---------------------------------------------------------------------------
// Attention via moment expansion (degree 12). One warp per row (1536 rows).
// Also zeroes g_y (for gemm2's split-K atomics).
// ---------------------------------------------------------------------------
#define NMOM 13
__global__ void attn_k()
{
    const int gtid = blockIdx.x * blockDim.x + threadIdx.x;
    if (gtid < (BATCH * CD * HW) / 4)
        ((float4*)g_y)[gtid] = make_float4(0.f, 0.f, 0.f, 0.f);

    const int row  = gtid >> 5;
    const int lane = threadIdx.x & 31;
    const int b = row / TD;
    const int r = row - b * TD;
    const float* base = g_qkv + (size_t)b * O3 * HW;
    const float4* q4 = (const float4*)(base + (size_t)r * HW);
    const float4* k4 = (const float4*)(base + (size_t)(TD + r) * HW);
    const float4* v4 = (const float4*)(base + (size_t)(2 * TD + r) * HW);

    float S[NMOM], T[NMOM];
    #pragma unroll
    for (int m = 0; m < NMOM; m++) { S[m] = 0.f; T[m] = 0.f; }

    #pragma unroll
    for (int c = 0; c < 2; c++) {
        float4 kk = k4[lane + 32 * c];
        float4 vv = v4[lane + 32 * c];
        float ks[4] = {kk.x, kk.y, kk.z, kk.w};
        float vs[4] = {vv.x, vv.y, vv.z, vv.w};
        #pragma unroll
        for (int e = 0; e < 4; e++) {
            float pw = 1.f;
            float kv = ks[e], vl = vs[e];
            #pragma unroll
            for (int m = 0; m < NMOM; m++) {
                S[m] = fmaf(pw, vl, S[m]);
                T[m] += pw;
                pw *= kv;
            }
        }
    }

    const float invf[NMOM] = {
        1.f, 1.f, 0.5f, 1.f/6.f, 1.f/24.f, 1.f/120.f, 1.f/720.f,
        1.f/5040.f, 1.f/40320.f, 1.f/362880.f, 1.f/3628800.f,
        1.f/39916800.f, 1.f/479001600.f };

    #pragma unroll
    for (int m = 0; m < NMOM; m++) {
        #pragma unroll
        for (int o = 16; o > 0; o >>= 1) {
            S[m] += __shfl_xor_sync(0xffffffffu, S[m], o);
            T[m] += __shfl_xor_sync(0xffffffffu, T[m], o);
        }
        S[m] *= invf[m];
        T[m] *= invf[m];
    }

    float* orow = g_att + (size_t)row * HW;
    #pragma unroll
    for (int c = 0; c < 2; c++) {
        float4 qq = q4[lane + 32 * c];
        float qs[4] = {qq.x, qq.y, qq.z, qq.w};
        float os[4];
        #pragma unroll
        for (int e = 0; e < 4; e++) {
            float p = qs[e] * SCALE;
            float num = S[NMOM - 1], den = T[NMOM - 1];
            #pragma unroll
            for (int m = NMOM - 2; m >= 0; m--) {
                num = fmaf(num, p, S[m]);
                den = fmaf(den, p, T[m]);
            }
            os[e] = __fdividef(num, den);
        }
        float4 o4 = {os[0], os[1], os[2], os[3]};
        *(float4*)&orow[(lane + 32 * c) * 4] = o4;
    }
}

// ---------------------------------------------------------------------------
// GEMM2 (bf16 HMMA + ldmatrix, fragment-pipelined, split-K x4, atomicAdd):
// partial y = w_out @ att.  C zeroed by attn_k.
// Block tile 64(M)x64(N), BK=64, 256 threads = 8 warps (2M x 4N),
// warp tile 32x16. KSLICE=192 -> 3 slices.
// ---------------------------------------------------------------------------
#define SPLITK 4
#define KSLICE (TD / SPLITK)   // 192
__global__ __launch_bounds__(256) void gemm2_k(const float* __restrict__ A,
                                               const float* __restrict__ Bg,
                                               float* __restrict__ Cg)
{
    __shared__ unsigned As[64][SROWW];
    __shared__ unsigned Bs[64][SROWW];

    const int zb = blockIdx.z;
    const int bz = zb >> 2;
    const int ks = zb & 3;
    const float* Bb = Bg + (size_t)bz * TD * HW;
    float*       Cb = Cg + (size_t)bz * CD * HW;

    const int tid  = threadIdx.x;
    const int wid  = tid >> 5;
    const int lane = tid & 31;
    const int q    = lane >> 2;
    const int t    = lane & 3;
    const int m0   = (wid >> 2) * 32;
    const int n0   = (wid & 3) * 16;
    const int row0 = blockIdx.y * 64;
    const int col0 = blockIdx.x * 64;
    const int kbeg = ks * KSLICE;

    const int lrow = (lane & 7) + ((lane >> 3) & 1) * 8;
    const int lcol = (lane >> 4) * 8;
    const unsigned a_base = sptr(As) + (unsigned)(((m0 + lrow) * SROW + lcol) * 2);
    const unsigned b_base = sptr(Bs) + (unsigned)((lrow * SROW + n0 + lcol) * 2);

    float acc[2][2][4];
    #pragma unroll
    for (int im = 0; im < 2; im++)
        #pragma unroll
        for (int jn = 0; jn < 2; jn++)
            #pragma unroll
            for (int e = 0; e < 4; e++) acc[im][jn][e] = 0.f;

    float4 pa[4];
    float4 pb0[2], pb1[2];

    #define LDG_SLICE2(k0)                                                       \
    {                                                                            \
        _Pragma("unroll")                                                        \
        for (int u = 0; u < 4; u++) {                                            \
            int idx = tid + u * 256;                                             \
            int m = idx >> 4, j4 = idx & 15;                                     \
            pa[u] = *(const float4*)&A[(size_t)(row0 + m) * TD + (k0) + j4 * 4]; \
        }                                                                        \
        _Pragma("unroll")                                                        \
        for (int u = 0; u < 2; u++) {                                            \
            int idx = tid + u * 256;                                             \
            int k2 = idx >> 4, n4 = idx & 15;                                    \
            const float* p = &Bb[(size_t)((k0) + 2 * k2) * HW + col0 + n4 * 4];  \
            pb0[u] = *(const float4*)p;                                          \
            pb1[u] = *(const float4*)(p + HW);                                   \
        }                                                                        \
    }

    #define STS_SLICE2()                                                         \
    {                                                                            \
        _Pragma("unroll")                                                        \
        for (int u = 0; u < 4; u++) {                                            \
            int idx = tid + u * 256;                                             \
            int m = idx >> 4, j4 = idx & 15;                                     \
            uint2 w = {bf2(pa[u].y, pa[u].x), bf2(pa[u].w, pa[u].z)};            \
            *(uint2*)&As[m][j4 * 2] = w;                                         \
        }                                                                        \
        _Pragma("unroll")                                                        \
        for (int u = 0; u < 2; u++) {                                            \
            int idx = tid + u * 256;                                             \
            int k2 = idx >> 4, n4 = idx & 15;                                    \
            uint2 w0 = {bf2(pb0[u].y, pb0[u].x), bf2(pb0[u].w, pb0[u].z)};       \
            uint2 w1 = {bf2(pb1[u].y, pb1[u].x), bf2(pb1[u].w, pb1[u].z)};       \
            *(uint2*)&Bs[2 * k2][n4 * 2]     = w0;                               \
            *(uint2*)&Bs[2 * k2 + 1][n4 * 2] = w1;                               \
        }                                                                        \
    }

    #define LDF2(d, kq)                                                          \
    {                                                                            \
        ldsm4(af[d][0], a_base + (kq) * 32);                                     \
        ldsm4(af[d][1], a_base + 16 * SROW * 2 + (kq) * 32);                     \
        ldsm4t(bfr[d], b_base + (kq) * 16 * SROW * 2);                           \
    }

    unsigned af[2][2][4], bfr[2][4];

    LDG_SLICE2(kbeg);
    #pragma unroll
    for (int s = 0; s < 3; s++) {            // KSLICE/64 = 3 slices
        STS_SLICE2();
        __syncthreads();
        if (s + 1 < 3) LDG_SLICE2(kbeg + (s + 1) * 64);

        LDF2(0, 0);
        #pragma unroll
        for (int kq = 0; kq < 4; kq++) {
            const int cur = kq & 1;
            if (kq + 1 < 4) LDF2(cur ^ 1, kq + 1);
            #pragma unroll
            for (int im = 0; im < 2; im++)
                #pragma unroll
                for (int jn = 0; jn < 2; jn++)
                    mma_bf16(acc[im][jn],
                             af[cur][im][0], af[cur][im][1],
                             af[cur][im][2], af[cur][im][3],
                             bfr[cur][jn * 2], bfr[cur][jn * 2 + 1]);
        }
        __syncthreads();
    }
    #undef LDG_SLICE2
    #undef STS_SLICE2
    #undef LDF2

    #pragma unroll
    for (int im = 0; im < 2; im++) {
        int r = row0 + m0 + im * 16 + q;
        #pragma unroll
        for (int jn = 0; jn < 2; jn++) {
            int c = col0 + n0 + jn * 8 + 2 * t;
            atomicAdd(&Cb[(size_t)r * HW + c],           acc[im][jn][0]);
            atomicAdd(&Cb[(size_t)r * HW + c + 1],       acc[im][jn][1]);
            atomicAdd(&Cb[(size_t)(r + 8) * HW + c],     acc[im][jn][2]);
            atomicAdd(&Cb[(size_t)(r + 8) * HW + c + 1], acc[im][jn][3]);
        }
    }
}

// ---------------------------------------------------------------------------
// LayerNorm + bias + residual. One warp per row (b,c), 8 elems/lane.
// ---------------------------------------------------------------------------
__global__ __launch_bounds__(256) void ln2_k(const float* __restrict__ x,
                                             const float* __restrict__ b_out,
                                             float* __restrict__ out)
{
    const int row  = (blockIdx.x * blockDim.x + threadIdx.x) >> 5;
    const int lane = threadIdx.x & 31;
    const int c = row & (CD - 1);
    const float4* yrow = (const float4*)(g_y + (size_t)row * HW);
    const float4* xrow = (const float4*)(x + (size_t)row * HW);
    const float bias = b_out[c];

    float4 v[2];
    float s = 0.f, s2 = 0.f;
    #pragma unroll
    for (int t = 0; t < 2; t++) {
        float4 a = yrow[lane + 32 * t];
        float4 bb = xrow[lane + 32 * t];
        a.x += bb.x + bias; a.y += bb.y + bias;
        a.z += bb.z + bias; a.w += bb.w + bias;
        v[t] = a;
        s  += a.x + a.y + a.z + a.w;
        s2 += a.x * a.x + a.y * a.y + a.z * a.z + a.w * a.w;
    }
    #pragma unroll
    for (int o = 16; o > 0; o >>= 1) {
        s  += __shfl_xor_sync(0xffffffffu, s,  o);
        s2 += __shfl_xor_sync(0xffffffffu, s2, o);
    }
    const float mean = s * (1.f / HW);
    const float var  = s2 * (1.f / HW) - mean * mean;
    const float inv  = rsqrtf(var + 1e-5f);

    float4* orow = (float4*)(out + (size_t)row * HW);
    #pragma unroll
    for (int t = 0; t < 2; t++) {
        float4 a = v[t];
        a.x = (a.x - mean) * inv; a.y = (a.y - mean) * inv;
        a.z = (a.z - mean) * inv; a.w = (a.w - mean) * inv;
        orow[lane + 32 * t] = a;
    }
}

// ---------------------------------------------------------------------------
extern "C" void kernel_launch(void* const* d_in, const int* in_sizes, int n_in,
                              void* d_out, int out_size)
{
    const float* x     = (const float*)d_in[0];   // (2,256,16,16)
    const float* w_qkv = (const float*)d_in[1];   // (2304,256)
    const float* w_out = (const float*)d_in[2];   // (256,768)
    const float* b_out = (const float*)d_in[3];   // (256,)
    float* out = (float*)d_out;                   // (2,256,16,16) fp32

    float *qkv_p, *att_p, *y_p;
    cudaGetSymbolAddress((void**)&qkv_p, g_qkv);
    cudaGetSymbolAddress((void**)&att_p, g_att);
    cudaGetSymbolAddress((void**)&y_p,   g_y);

    // 1) qkv = w_qkv @ x   (bf16 HMMA + LDSM, pipelined, 144 blocks)
    gemm1_k<<<dim3(HW / 64, O3 / 128, BATCH), 256>>>(w_qkv, x, qkv_p);

    // 2) moment-expansion attention (+ zero g_y)
    attn_k<<<(BATCH * TD * 32) / 256, 256>>>();

    // 3) y(partial) = w_out @ att, pipelined, split-K x4
    gemm2_k<<<dim3(HW / 64, CD / 64, BATCH * SPLITK), 256>>>(w_out, att_p, y_p);

    // 4) LayerNorm(+bias+residual), warp per row
    ln2_k<<<(BATCH * CD * 32) / 256, 256>>>(x, b_out, out);
}